// round 16
// baseline (speedup 1.0000x reference)
#include <cuda_runtime.h>
#include <cuda_fp16.h>
#include <cstdint>

// out[128,1024] = x[128,1024] @ (w_pos - w_neg)[1024,1024] + (b_pos - b_neg)
// Memristor scaling cancels exactly; fp16 single-pass HMMA (fp32 accumulate),
// rel_err ~3e-4 (validated r14).
//
// Round 16: SINGLE kernel. No init kernel, no split-K atomics, no inter-kernel
// dependency (~2-3us launch overhead each + atomic round-trips were the
// invariant cost across all prior variants). CTA owns a 32M x 32N output tile
// over full K=1024; K split x4 across warps inside the CTA; smem reduce; bias
// added in epilogue; direct STG.128.

#define BATCH 128
#define NIN   1024
#define NOUT  1024
#define MT    32        // M per CTA
#define NTB   32        // N per CTA
#define RA    2064      // A row stride bytes (1024 fp16 = 2048 + 16 pad)
#define RB    80        // B k-row stride bytes (32 fp16 = 64 + 16 pad)
#define A_OFF 0
#define B_OFF (MT * RA)                   // 66048
#define P_OFF (B_OFF + NIN * RB)          // 147968
#define SMEM_TOTAL (P_OFF + 2 * 4 * 16 * 32 * 4)   // +16384 = 164352

__device__ __forceinline__ uint32_t smem_u32(const void* p) {
    uint32_t a;
    asm("{ .reg .u64 t; cvta.to.shared.u64 t, %1; cvt.u32.u64 %0, t; }" : "=r"(a) : "l"(p));
    return a;
}
__device__ __forceinline__ void ldsm4(uint32_t* r, uint32_t a) {
    asm volatile("ldmatrix.sync.aligned.m8n8.x4.shared.b16 {%0,%1,%2,%3}, [%4];"
                 : "=r"(r[0]), "=r"(r[1]), "=r"(r[2]), "=r"(r[3]) : "r"(a));
}
__device__ __forceinline__ void ldsm4t(uint32_t* r, uint32_t a) {
    asm volatile("ldmatrix.sync.aligned.m8n8.x4.trans.shared.b16 {%0,%1,%2,%3}, [%4];"
                 : "=r"(r[0]), "=r"(r[1]), "=r"(r[2]), "=r"(r[3]) : "r"(a));
}
__device__ __forceinline__ void mma16816h(float* d, const uint32_t* a,
                                          uint32_t b0, uint32_t b1) {
    asm volatile("mma.sync.aligned.m16n8k16.row.col.f32.f16.f16.f32 "
                 "{%0,%1,%2,%3}, {%4,%5,%6,%7}, {%8,%9}, {%0,%1,%2,%3};"
                 : "+f"(d[0]), "+f"(d[1]), "+f"(d[2]), "+f"(d[3])
                 : "r"(a[0]), "r"(a[1]), "r"(a[2]), "r"(a[3]), "r"(b0), "r"(b1));
}
__device__ __forceinline__ uint64_t pack4h(float a, float b, float c, float d) {
    uint16_t h0 = __half_as_ushort(__float2half_rn(a));
    uint16_t h1 = __half_as_ushort(__float2half_rn(b));
    uint16_t h2 = __half_as_ushort(__float2half_rn(c));
    uint16_t h3 = __half_as_ushort(__float2half_rn(d));
    return (uint64_t)h0 | ((uint64_t)h1 << 16) | ((uint64_t)h2 << 32) | ((uint64_t)h3 << 48);
}

// grid (32 jt, 4 mt) = 128 CTAs; 256 threads
extern "C" __global__ void __launch_bounds__(256, 1)
memr_fused(const float* __restrict__ x,
           const float* __restrict__ wp,
           const float* __restrict__ wn,
           const float* __restrict__ bp,
           const float* __restrict__ bn,
           float* __restrict__ out) {
    extern __shared__ char smem_raw[];
    const uint32_t SB = smem_u32(smem_raw);
    const uint32_t A  = SB + A_OFF;     // x tile  [32 m][1024 k] fp16
    const uint32_t B  = SB + B_OFF;     // d tile  [1024 k][32 o] fp16
    float* part = reinterpret_cast<float*>(smem_raw + P_OFF);  // [2][4][16][32]

    const int t  = threadIdx.x;
    const int j0 = blockIdx.x * NTB;
    const int m0 = blockIdx.y * MT;

    // ---- A tile: x[m0:m0+32, :] fp32 -> fp16, coalesced float4 ----
    // 8192 float4, 32 per thread (256 f4 per row)
#pragma unroll 4
    for (int i = 0; i < 32; i++) {
        int id  = t + 256 * i;
        int row = id >> 8;
        int f4  = id & 255;
        float4 v = *reinterpret_cast<const float4*>(x + (size_t)(m0 + row) * NIN + f4 * 4);
        uint32_t off = (uint32_t)row * RA + (uint32_t)f4 * 8;
        asm volatile("st.shared.b64 [%0], %1;" :: "r"(A + off), "l"(pack4h(v.x, v.y, v.z, v.w)) : "memory");
    }

    // ---- B tile: (wp-wn)[:, j0:j0+32] fp32 -> fp16 ----
    // 8192 float4 per matrix, 32 per thread (8 f4 per k-row)
#pragma unroll 4
    for (int i = 0; i < 32; i++) {
        int id   = t + 256 * i;
        int krow = id >> 3;
        int f4   = id & 7;
        const float4 p = *reinterpret_cast<const float4*>(wp + (size_t)krow * NOUT + j0 + f4 * 4);
        const float4 n = *reinterpret_cast<const float4*>(wn + (size_t)krow * NOUT + j0 + f4 * 4);
        uint32_t off = (uint32_t)krow * RB + (uint32_t)f4 * 8;
        asm volatile("st.shared.b64 [%0], %1;"
                     :: "r"(B + off), "l"(pack4h(p.x - n.x, p.y - n.y, p.z - n.z, p.w - n.w)) : "memory");
    }
    __syncthreads();

    // ---- compute: 8 warps = 2(M half, 16 rows) x 4(K quarter, 256 k) ----
    const int wid  = t >> 5;
    const int lane = t & 31;
    const int wm = wid >> 2;          // m half
    const int kq = wid & 3;           // k quarter
    const int kbase = kq * 256;

    float acc[4][4];                  // 4 n8 frags over 32 cols
#pragma unroll
    for (int n = 0; n < 4; n++)
#pragma unroll
        for (int i = 0; i < 4; i++) acc[n][i] = 0.0f;

    const uint32_t aP = A + (uint32_t)(wm * 16 + (lane & 15)) * RA +
                        (uint32_t)((lane >> 4) * 16) + (uint32_t)kbase * 2;
    const uint32_t bP = B + (uint32_t)(kbase + (lane & 15)) * RB +
                        (uint32_t)((lane >> 4) * 8) * 2;

#pragma unroll
    for (int s = 0; s < 16; s++) {            // 16 k16-steps within quarter
        uint32_t a[4], b0[4], b1[4];
        ldsm4 (a,  aP + (uint32_t)s * 32);
        ldsm4t(b0, bP + (uint32_t)(s * 16) * RB);        // cols 0-15
        ldsm4t(b1, bP + (uint32_t)(s * 16) * RB + 32);   // cols 16-31
        mma16816h(acc[0], a, b0[0], b0[1]);
        mma16816h(acc[1], a, b0[2], b0[3]);
        mma16816h(acc[2], a, b1[0], b1[1]);
        mma16816h(acc[3], a, b1[2], b1[3]);
    }

    // ---- store warp partial to smem: part[wm][kq][16][32] ----
    {
        const int r = lane >> 2;
        const int c = 2 * (lane & 3);
        float* base = part + ((wm * 4 + kq) * 16) * 32;
#pragma unroll
        for (int n = 0; n < 4; n++) {
            float* p0 = base + (size_t)r * 32 + c + n * 8;
            p0[0] = acc[n][0];
            p0[1] = acc[n][1];
            float* p1 = base + (size_t)(r + 8) * 32 + c + n * 8;
            p1[0] = acc[n][2];
            p1[1] = acc[n][3];
        }
    }
    __syncthreads();

    // ---- reduce 4 K-quarters + bias, direct STG.128 ----
    {
        const int row  = t >> 3;          // 0..31
        const int col  = (t & 7) * 4;     // 0..28
        const int wh   = row >> 4;
        const int r    = row & 15;

        float4 vp = *reinterpret_cast<const float4*>(bp + j0 + col);
        float4 vn = *reinterpret_cast<const float4*>(bn + j0 + col);
        float4 s  = make_float4(vp.x - vn.x, vp.y - vn.y, vp.z - vn.z, vp.w - vn.w);
#pragma unroll
        for (int k = 0; k < 4; k++) {
            const float4 q = *reinterpret_cast<const float4*>(
                part + ((wh * 4 + k) * 16 + r) * 32 + col);
            s.x += q.x; s.y += q.y; s.z += q.z; s.w += q.w;
        }
        *reinterpret_cast<float4*>(out + (size_t)(m0 + row) * NOUT + j0 + col) = s;
    }
}

extern "C" void kernel_launch(void* const* d_in, const int* in_sizes, int n_in,
                              void* d_out, int out_size) {
    const float* x  = (const float*)d_in[0];
    const float* wp = (const float*)d_in[1];
    const float* wn = (const float*)d_in[2];
    const float* bp = (const float*)d_in[3];
    const float* bn = (const float*)d_in[4];
    float* out = (float*)d_out;

    cudaFuncSetAttribute(memr_fused,
                         cudaFuncAttributeMaxDynamicSharedMemorySize, SMEM_TOTAL);

    dim3 grid(NOUT / NTB, BATCH / MT);    // 32 x 4 = 128 CTAs
    memr_fused<<<grid, 256, SMEM_TOTAL>>>(x, wp, wn, bp, bn, out);
}

// round 17
// speedup vs baseline: 1.1930x; 1.1930x over previous
#include <cuda_runtime.h>
#include <cuda_fp16.h>
#include <cstdint>

// out[128,1024] = x[128,1024] @ (w_pos - w_neg)[1024,1024] + (b_pos - b_neg)
// Memristor scaling cancels exactly; fp16 single-pass HMMA (fp32 accumulate),
// rel_err ~3e-4 (validated r14).
//
// Round 17: r14's GEMM body verbatim, but epilogue REDG -> plain STG.64 into
// an 8MB split-K scratch (spread-address red.v2 costs ~80cyc/warp-op of LSU
// serialization vs ~8 for STG; r14 had 32768 of them). Reduce kernel: 65K
// threads x 16 independent float2 loads (L2-resident) + bias -> out.
// No init kernel, no atomics anywhere.

#define BATCH 128
#define NIN   1024
#define NOUT  1024
#define KSPLIT 16
#define KCHUNK 64       // NIN / KSPLIT
#define TILE_N 64
#define NT 16           // NOUT / TILE_N
#define RA 144          // A smem row stride bytes (64 fp16 = 128B + 16 pad)
#define RB 144          // B smem row stride bytes (64 fp16 = 128B + 16 pad)

// split-K fp32 partials: 16 * 128 * 1024 floats = 8 MB (L2-resident)
__device__ float g_part[KSPLIT * BATCH * NOUT];

__device__ __forceinline__ uint32_t smem_u32(const void* p) {
    uint32_t a;
    asm("{ .reg .u64 t; cvta.to.shared.u64 t, %1; cvt.u32.u64 %0, t; }" : "=r"(a) : "l"(p));
    return a;
}
__device__ __forceinline__ void ldsm4(uint32_t* r, uint32_t a) {
    asm volatile("ldmatrix.sync.aligned.m8n8.x4.shared.b16 {%0,%1,%2,%3}, [%4];"
                 : "=r"(r[0]), "=r"(r[1]), "=r"(r[2]), "=r"(r[3]) : "r"(a));
}
__device__ __forceinline__ void ldsm4t(uint32_t* r, uint32_t a) {
    asm volatile("ldmatrix.sync.aligned.m8n8.x4.trans.shared.b16 {%0,%1,%2,%3}, [%4];"
                 : "=r"(r[0]), "=r"(r[1]), "=r"(r[2]), "=r"(r[3]) : "r"(a));
}
__device__ __forceinline__ void mma16816h(float* d, const uint32_t* a,
                                          uint32_t b0, uint32_t b1) {
    asm volatile("mma.sync.aligned.m16n8k16.row.col.f32.f16.f16.f32 "
                 "{%0,%1,%2,%3}, {%4,%5,%6,%7}, {%8,%9}, {%0,%1,%2,%3};"
                 : "+f"(d[0]), "+f"(d[1]), "+f"(d[2]), "+f"(d[3])
                 : "r"(a[0]), "r"(a[1]), "r"(a[2]), "r"(a[3]), "r"(b0), "r"(b1));
}
__device__ __forceinline__ uint64_t pack4h(float a, float b, float c, float d) {
    uint16_t h0 = __half_as_ushort(__float2half_rn(a));
    uint16_t h1 = __half_as_ushort(__float2half_rn(b));
    uint16_t h2 = __half_as_ushort(__float2half_rn(c));
    uint16_t h3 = __half_as_ushort(__float2half_rn(d));
    return (uint64_t)h0 | ((uint64_t)h1 << 16) | ((uint64_t)h2 << 32) | ((uint64_t)h3 << 48);
}

extern "C" __global__ void __launch_bounds__(256, 2)
memr_gemm_hmma(const float* __restrict__ x,
               const float* __restrict__ wp,
               const float* __restrict__ wn) {
    extern __shared__ char smem_raw[];
    const uint32_t A = smem_u32(smem_raw);        // x  [128 b][64 k] fp16
    const uint32_t B = A + 128 * RA;              // d  [64 k][64 o] fp16

    const int t  = threadIdx.x;
    const int jt = blockIdx.x;        // N tile (64 cols)
    const int ks = blockIdx.y;        // K split (64 k)
    const int k0 = ks * KCHUNK;
    const int j0 = jt * TILE_N;

    // ---- x tile: [128 b, k0:k0+64], coalesced float4 -> fp16 ----
#pragma unroll 4
    for (int i = 0; i < 8; i++) {
        int id  = t + 256 * i;
        int row = id >> 4;            // batch row (16 float4 per row)
        int kq  = id & 15;
        float4 v = *reinterpret_cast<const float4*>(x + (size_t)row * NIN + k0 + kq * 4);
        uint64_t hv = pack4h(v.x, v.y, v.z, v.w);
        uint32_t off = (uint32_t)row * RA + (uint32_t)kq * 8;
        asm volatile("st.shared.b64 [%0], %1;" :: "r"(A + off), "l"(hv) : "memory");
    }

    // ---- W tile: [64 k, 64 o] row-major coalesced, diff -> fp16 ----
#pragma unroll 4
    for (int i = 0; i < 4; i++) {
        int id = t + 256 * i;
        int k  = id >> 4;             // k row (16 float4 per row)
        int oq = id & 15;
        const float4 p = *reinterpret_cast<const float4*>(wp + (size_t)(k0 + k) * NOUT + j0 + oq * 4);
        const float4 n = *reinterpret_cast<const float4*>(wn + (size_t)(k0 + k) * NOUT + j0 + oq * 4);
        uint64_t hv = pack4h(p.x - n.x, p.y - n.y, p.z - n.z, p.w - n.w);
        uint32_t off = (uint32_t)k * RB + (uint32_t)oq * 8;
        asm volatile("st.shared.b64 [%0], %1;" :: "r"(B + off), "l"(hv) : "memory");
    }
    __syncthreads();

    // ---- compute: 8 warps as 4(M) x 2(N); warp tile 32 rows x 32 cols ----
    const int wid  = t >> 5;
    const int lane = t & 31;
    const int wm  = wid >> 1;         // rows 32*wm
    const int wn2 = wid & 1;          // cols 32*wn2

    float acc[2][4][4];
#pragma unroll
    for (int mt = 0; mt < 2; mt++)
#pragma unroll
        for (int n = 0; n < 4; n++)
#pragma unroll
            for (int i = 0; i < 4; i++) acc[mt][n][i] = 0.0f;

    const uint32_t aOff = (uint32_t)(wm * 32 + (lane & 15)) * RA + (uint32_t)((lane >> 4) * 16);
    const uint32_t bOff = (uint32_t)(lane & 15) * RB + (uint32_t)(wn2 * 32 + (lane >> 4) * 8) * 2;
    const uint32_t aP = A + aOff;
    const uint32_t bP = B + bOff;

#pragma unroll
    for (int s = 0; s < 4; s++) {                 // 4 k16-steps
        const uint32_t soA = (uint32_t)s * 32;    // 16 fp16 = 32B along k
        const uint32_t soB = (uint32_t)(s * 16) * RB;
        uint32_t a0[4], a1[4];
        ldsm4(a0, aP + soA);
        ldsm4(a1, aP + 16 * RA + soA);
        uint32_t br[2][4];
        ldsm4t(br[0], bP + soB);
        ldsm4t(br[1], bP + soB + 32);             // cols +16
#pragma unroll
        for (int n = 0; n < 4; n++) {
            const int g = n >> 1, j = n & 1;
            const uint32_t b0 = br[g][2 * j], b1 = br[g][2 * j + 1];
            mma16816h(acc[0][n], a0, b0, b1);
            mma16816h(acc[1][n], a1, b0, b1);
        }
    }

    // ---- epilogue: plain STG.64 into split-K scratch (no atomics) ----
    float* dst = g_part + (size_t)ks * (BATCH * NOUT);
    const int r0 = wm * 32 + (lane >> 2);
    const int c0 = j0 + wn2 * 32 + 2 * (lane & 3);
#pragma unroll
    for (int mt = 0; mt < 2; mt++) {
#pragma unroll
        for (int n = 0; n < 4; n++) {
            int row = r0 + mt * 16;
            int col = c0 + n * 8;
            *reinterpret_cast<float2*>(dst + (size_t)row * NOUT + col) =
                make_float2(acc[mt][n][0], acc[mt][n][1]);
            *reinterpret_cast<float2*>(dst + (size_t)(row + 8) * NOUT + col) =
                make_float2(acc[mt][n][2], acc[mt][n][3]);
        }
    }
}

// ---- reduce: 65536 threads, 16 independent float2 loads + bias -> out ----
extern "C" __global__ void __launch_bounds__(128)
memr_reduce(const float* __restrict__ bp,
            const float* __restrict__ bn,
            float* __restrict__ out) {
    int id   = blockIdx.x * 128 + threadIdx.x;   // 0..65535
    int base = id * 2;
    int o    = base & (NOUT - 1);

    float2 vp = *reinterpret_cast<const float2*>(bp + o);
    float2 vn = *reinterpret_cast<const float2*>(bn + o);
    float sx = vp.x - vn.x;
    float sy = vp.y - vn.y;

    float2 p[KSPLIT];
#pragma unroll
    for (int k = 0; k < KSPLIT; k++)
        p[k] = *reinterpret_cast<const float2*>(g_part + (size_t)k * (BATCH * NOUT) + base);
#pragma unroll
    for (int k = 0; k < KSPLIT; k++) { sx += p[k].x; sy += p[k].y; }

    *reinterpret_cast<float2*>(out + base) = make_float2(sx, sy);
}

extern "C" void kernel_launch(void* const* d_in, const int* in_sizes, int n_in,
                              void* d_out, int out_size) {
    const float* x  = (const float*)d_in[0];
    const float* wp = (const float*)d_in[1];
    const float* wn = (const float*)d_in[2];
    const float* bp = (const float*)d_in[3];
    const float* bn = (const float*)d_in[4];
    float* out = (float*)d_out;

    const int smem_bytes = 128 * RA + 64 * RB;   // 27648 (< 48KB default)

    dim3 grid(NT, KSPLIT);                        // 16 x 16 = 256 CTAs
    memr_gemm_hmma<<<grid, 256, smem_bytes>>>(x, wp, wn);
    memr_reduce<<<512, 128>>>(bp, bn, out);
}